// round 4
// baseline (speedup 1.0000x reference)
#include <cuda_runtime.h>
#include <cstdint>
#include <math.h>

// Sizes fixed: B=4, T=2048, E=1024, M=2048; R = B*T = 8192.
#define R_ROWS 8192
#define E_DIM  1024
#define M_DIM  2048
#define NCHUNK 16
#define TCH    128

// ---------------- scratch ----------------
__device__ float g_y [R_ROWS * E_DIM];
__device__ float g_b0[R_ROWS * M_DIM];
__device__ float g_b1[R_ROWS * M_DIM];   // yi (fp32) / zi (tf32-truncated)
__device__ float g_r [R_ROWS * M_DIM];
__device__ float g_og[R_ROWS * M_DIM];
__device__ float g_g [R_ROWS * M_DIM];
__device__ float g_x2[R_ROWS * E_DIM];
__device__ float g_z [R_ROWS * E_DIM];
__device__ float g_Ac[NCHUNK * 8192];
__device__ float g_Sc[NCHUNK * 8192];
__device__ float g_Hc[NCHUNK * 8192];
#define WSLOT (E_DIM * M_DIM)
__device__ float g_wT[8 * WSLOT];        // tf32-truncated weights

__device__ __forceinline__ float sigm(float x) { return 1.f / (1.f + __expf(-x)); }

__device__ __forceinline__ uint32_t smem_u32(const void* p) {
    uint32_t a;
    asm("{ .reg .u64 t; cvta.to.shared.u64 t, %1; cvt.u32.u64 %0, t; }" : "=r"(a) : "l"(p));
    return a;
}

#define CP_ASYNC16(dst, src) asm volatile("cp.async.cg.shared.global [%0], [%1], 16;" :: "r"(dst), "l"(src))
#define CP_COMMIT()          asm volatile("cp.async.commit_group;" ::: "memory")
#define CP_WAIT1()           asm volatile("cp.async.wait_group 1;" ::: "memory")

__device__ __forceinline__ float f2tf32f(float v) {
    uint32_t r;
    asm("cvt.rna.tf32.f32 %0, %1;" : "=r"(r) : "f"(v));
    return __uint_as_float(r);
}

#define MMA_TF32(c, a, b)                                                      \
    asm volatile("mma.sync.aligned.m16n8k8.row.col.f32.tf32.tf32.f32 "         \
        "{%0,%1,%2,%3}, {%4,%5,%6,%7}, {%8,%9}, {%0,%1,%2,%3};"                \
        : "+f"((c)[0]), "+f"((c)[1]), "+f"((c)[2]), "+f"((c)[3])               \
        : "r"((a)[0]), "r"((a)[1]), "r"((a)[2]), "r"((a)[3]),                  \
          "r"((b)[0]), "r"((b)[1]))

// ---------------- weight convert: fp32 -> tf32(rna) bits ----------------
__global__ __launch_bounds__(256) void cvt_tf32(const float* __restrict__ src,
                                                float* __restrict__ dst) {
    int i = blockIdx.x * 256 + threadIdx.x;
    float4 v = ((const float4*)src)[i];
    v.x = f2tf32f(v.x); v.y = f2tf32f(v.y); v.z = f2tf32f(v.z); v.w = f2tf32f(v.w);
    ((float4*)dst)[i] = v;
}

// ---------------- LayerNorm (rows of 1024), tf32-truncated output ----------------
__global__ __launch_bounds__(256) void ln1024(const float* __restrict__ x,
                                              const float* __restrict__ w,
                                              const float* __restrict__ b,
                                              float* __restrict__ y) {
    int row = blockIdx.x;
    const float4* xr = (const float4*)(x + (size_t)row * 1024);
    float4 v = xr[threadIdx.x];
    float s = v.x + v.y + v.z + v.w;
    float q = v.x * v.x + v.y * v.y + v.z * v.z + v.w * v.w;
#pragma unroll
    for (int o = 16; o; o >>= 1) {
        s += __shfl_xor_sync(0xFFFFFFFF, s, o);
        q += __shfl_xor_sync(0xFFFFFFFF, q, o);
    }
    __shared__ float ss[8], sq[8];
    int wid = threadIdx.x >> 5, lane = threadIdx.x & 31;
    if (lane == 0) { ss[wid] = s; sq[wid] = q; }
    __syncthreads();
    s = 0.f; q = 0.f;
#pragma unroll
    for (int i = 0; i < 8; i++) { s += ss[i]; q += sq[i]; }
    float mu  = s * (1.f / 1024.f);
    float var = q * (1.f / 1024.f) - mu * mu;
    float inv = rsqrtf(var + 1e-5f);
    float4 wv = ((const float4*)w)[threadIdx.x];
    float4 bv = ((const float4*)b)[threadIdx.x];
    float4 o;
    o.x = f2tf32f((v.x - mu) * inv * wv.x + bv.x);
    o.y = f2tf32f((v.y - mu) * inv * wv.y + bv.y);
    o.z = f2tf32f((v.z - mu) * inv * wv.z + bv.z);
    o.w = f2tf32f((v.w - mu) * inv * wv.w + bv.w);
    ((float4*)(y + (size_t)row * 1024))[threadIdx.x] = o;
}

// ---------------- tf32 mma.sync GEMM (operands pre-truncated) ----------------
// C[m][n] = epi( sum_k A[m][k] * B[k][n] ),  A:[M,K] rm, B:[K,N] rm.
// mode 0: store raw
//      1: sigmoid(acc+bias)
//      2: resid*sigmoid(acc+bias)            (fp32 store)
//      3: acc(+bias)+resid
//      4: tf32( resid*sigmoid(acc+bias) )    (tf32-truncated store)
#define ASTRIDE 36
#define BSTRIDE 132
#define ASTAGE  (128 * ASTRIDE)
#define BSTAGE  (32 * BSTRIDE)
#define GSMEM   ((2 * ASTAGE + 2 * BSTAGE) * 4)

__global__ __launch_bounds__(256, 2) void gemm_mma(const float* __restrict__ A,
                                                   const float* __restrict__ B,
                                                   const float* __restrict__ bias,
                                                   const float* __restrict__ resid,
                                                   float* __restrict__ C,
                                                   int K, int N, int mode) {
    extern __shared__ char smem[];
    const uint32_t* swi = (const uint32_t*)smem;
    uint32_t sbase = smem_u32(smem);

    int tid = threadIdx.x;
    int wid = tid >> 5, lane = tid & 31;
    int wm = wid & 3, wn = wid >> 2;
    int m0 = wm * 32, n0 = wn * 64;
    int grp = lane >> 2, ktid = lane & 3;
    int brow = blockIdx.y * 128, bcol = blockIdx.x * 128;

    const float* gA = A + (size_t)(brow + (tid >> 1)) * K + (tid & 1) * 16;
    const float* gB = B + (size_t)(tid >> 3) * N + bcol + (tid & 7) * 4;
    uint32_t dA = sbase + (uint32_t)(tid >> 1) * (ASTRIDE * 4) + (uint32_t)(tid & 1) * 64;
    uint32_t dB = sbase + 2u * ASTAGE * 4 + (uint32_t)(tid >> 3) * (BSTRIDE * 4) + (uint32_t)(tid & 7) * 16;

    float acc[2][8][4];
#pragma unroll
    for (int i = 0; i < 2; i++)
#pragma unroll
        for (int j = 0; j < 8; j++)
#pragma unroll
            for (int v = 0; v < 4; v++) acc[i][j][v] = 0.f;

    const int nk = K / 32;

#pragma unroll
    for (int u = 0; u < 4; u++) CP_ASYNC16(dA + u * 16, gA + u * 4);
#pragma unroll
    for (int u = 0; u < 4; u++) CP_ASYNC16(dB + u * 128, gB + u * 32);
    CP_COMMIT();

    // per-thread fragment bases (word offsets)
    int aoff0 = (m0 + grp) * ASTRIDE + ktid;
    int boff0 = ktid * BSTRIDE + n0 + grp;

    for (int kt = 0; kt < nk; kt++) {
        int cur = kt & 1;
        if (kt + 1 < nk) {
            int nxt = cur ^ 1;
            const float* a = gA + (kt + 1) * 32;
            const float* b = gB + (size_t)(kt + 1) * 32 * N;
            uint32_t da = dA + (uint32_t)nxt * (ASTAGE * 4);
            uint32_t db = dB + (uint32_t)nxt * (BSTAGE * 4);
#pragma unroll
            for (int u = 0; u < 4; u++) CP_ASYNC16(da + u * 16, a + u * 4);
#pragma unroll
            for (int u = 0; u < 4; u++) CP_ASYNC16(db + u * 128, b + u * 32);
        }
        CP_COMMIT();
        CP_WAIT1();
        __syncthreads();

        const uint32_t* cA = swi + cur * ASTAGE;
        const uint32_t* cB = swi + 2 * ASTAGE + cur * BSTAGE;

#pragma unroll
        for (int ks = 0; ks < 4; ks++) {
            uint32_t af[2][4], bf[8][2];
#pragma unroll
            for (int mi = 0; mi < 2; mi++) {
                const uint32_t* p = cA + aoff0 + mi * 16 * ASTRIDE + ks * 8;
                af[mi][0] = p[0];
                af[mi][1] = p[8 * ASTRIDE];
                af[mi][2] = p[4];
                af[mi][3] = p[8 * ASTRIDE + 4];
            }
#pragma unroll
            for (int ni = 0; ni < 8; ni++) {
                const uint32_t* q = cB + boff0 + ks * 8 * BSTRIDE + ni * 8;
                bf[ni][0] = q[0];
                bf[ni][1] = q[4 * BSTRIDE];
            }
#pragma unroll
            for (int mi = 0; mi < 2; mi++)
#pragma unroll
                for (int ni = 0; ni < 8; ni++)
                    MMA_TF32(acc[mi][ni], af[mi], bf[ni]);
        }
        __syncthreads();
    }

    // ---------------- epilogue ----------------
#pragma unroll
    for (int mi = 0; mi < 2; mi++) {
#pragma unroll
        for (int ni = 0; ni < 8; ni++) {
            int row = brow + m0 + mi * 16 + grp;
            int col = bcol + n0 + ni * 8 + ktid * 2;
            float b0v = 0.f, b1v = 0.f;
            if ((mode != 0) && bias) { b0v = bias[col]; b1v = bias[col + 1]; }
#pragma unroll
            for (int half = 0; half < 2; half++) {
                int r = row + half * 8;
                float v0 = acc[mi][ni][half * 2 + 0] + b0v;
                float v1 = acc[mi][ni][half * 2 + 1] + b1v;
                if (mode == 1 || mode == 2 || mode == 4) { v0 = sigm(v0); v1 = sigm(v1); }
                size_t off = (size_t)r * N + col;
                if (mode == 2 || mode == 4) {
                    float2 rr = *(const float2*)(resid + off);
                    v0 *= rr.x; v1 *= rr.y;
                    if (mode == 4) { v0 = f2tf32f(v0); v1 = f2tf32f(v1); }
                } else if (mode == 3) {
                    float2 rr = *(const float2*)(resid + off);
                    v0 += rr.x; v1 += rr.y;
                }
                float2 o; o.x = v0; o.y = v1;
                *(float2*)(C + off) = o;
            }
        }
    }
}

// ---------------- chunked scan: h_t = r_t*h_{t-1} + yi_t ----------------
__global__ __launch_bounds__(256) void scan_pass1(const float* __restrict__ yi,
                                                  const float* __restrict__ rb,
                                                  float* __restrict__ Ac,
                                                  float* __restrict__ Sc) {
    int idx = blockIdx.x * 256 + threadIdx.x;
    int ch  = idx & 8191;
    int c   = idx >> 13;
    int b   = ch >> 11;
    int base = (b * 2048 + c * TCH) * 2048 + (ch & 2047);
    float A = 1.f, S = 0.f;
#pragma unroll 4
    for (int t = 0; t < TCH; t++) {
        float rr = rb[base];
        S = fmaf(rr, S, yi[base]);
        A *= rr;
        base += 2048;
    }
    Ac[idx] = A;
    Sc[idx] = S;
}

__global__ __launch_bounds__(256) void scan_pass2(const float* __restrict__ mem,
                                                  const float* __restrict__ Ac,
                                                  const float* __restrict__ Sc,
                                                  float* __restrict__ Hc,
                                                  float* __restrict__ memout) {
    int ch = blockIdx.x * 256 + threadIdx.x;
    float h = mem[ch];
#pragma unroll
    for (int c = 0; c < NCHUNK; c++) {
        int i = c * 8192 + ch;
        Hc[i] = h;
        h = fmaf(Ac[i], h, Sc[i]);
    }
    memout[ch] = h;
}

__global__ __launch_bounds__(256) void scan_pass3(const float* __restrict__ yi,
                                                  const float* __restrict__ rb,
                                                  const float* __restrict__ og,
                                                  const float* __restrict__ Hc,
                                                  float* __restrict__ g) {
    int idx = blockIdx.x * 256 + threadIdx.x;
    int ch  = idx & 8191;
    int c   = idx >> 13;
    int b   = ch >> 11;
    int base = (b * 2048 + c * TCH) * 2048 + (ch & 2047);
    float h = Hc[idx];
#pragma unroll 4
    for (int t = 0; t < TCH; t++) {
        float rr = rb[base];
        h = fmaf(rr, h, yi[base]);
        float s = h / (1.f + fabsf(h));
        g[base] = f2tf32f(s * og[base]);   // tf32: g is GEMM-A-only
        base += 2048;
    }
}

// ---------------- host launch ----------------
extern "C" void kernel_launch(void* const* d_in, const int* in_sizes, int n_in,
                              void* d_out, int out_size) {
    const float* x    = (const float*)d_in[0];
    const float* mem  = (const float*)d_in[1];
    const float* ln1w = (const float*)d_in[2];
    const float* ln1b = (const float*)d_in[3];
    const float* wf   = (const float*)d_in[4];
    const float* wfb  = (const float*)d_in[5];
    const float* wi   = (const float*)d_in[6];
    const float* wig  = (const float*)d_in[7];
    const float* wigb = (const float*)d_in[8];
    const float* wog  = (const float*)d_in[9];
    const float* wogb = (const float*)d_in[10];
    const float* wo   = (const float*)d_in[11];
    const float* ln2w = (const float*)d_in[12];
    const float* ln2b = (const float*)d_in[13];
    const float* fwi  = (const float*)d_in[14];
    const float* fwg  = (const float*)d_in[15];
    const float* fwgb = (const float*)d_in[16];
    const float* fwo  = (const float*)d_in[17];
    const float* fwob = (const float*)d_in[18];
    float* out = (float*)d_out;

    float *y, *b0, *b1, *rb, *og, *g, *x2, *z, *Ac, *Sc, *Hc, *wT;
    cudaGetSymbolAddress((void**)&y,  g_y);
    cudaGetSymbolAddress((void**)&b0, g_b0);
    cudaGetSymbolAddress((void**)&b1, g_b1);
    cudaGetSymbolAddress((void**)&rb, g_r);
    cudaGetSymbolAddress((void**)&og, g_og);
    cudaGetSymbolAddress((void**)&g,  g_g);
    cudaGetSymbolAddress((void**)&x2, g_x2);
    cudaGetSymbolAddress((void**)&z,  g_z);
    cudaGetSymbolAddress((void**)&Ac, g_Ac);
    cudaGetSymbolAddress((void**)&Sc, g_Sc);
    cudaGetSymbolAddress((void**)&Hc, g_Hc);
    cudaGetSymbolAddress((void**)&wT, g_wT);

    cudaFuncSetAttribute(gemm_mma, cudaFuncAttributeMaxDynamicSharedMemorySize, GSMEM);

    float* wiC  = wT + 0 * WSLOT;
    float* wigC = wT + 1 * WSLOT;
    float* wfC  = wT + 2 * WSLOT;
    float* wogC = wT + 3 * WSLOT;
    float* woC  = wT + 4 * WSLOT;
    float* fwiC = wT + 5 * WSLOT;
    float* fwgC = wT + 6 * WSLOT;
    float* fwoC = wT + 7 * WSLOT;

    int cg = WSLOT / 4 / 256;   // 2048 blocks
    cvt_tf32<<<cg, 256>>>(wi,  wiC);
    cvt_tf32<<<cg, 256>>>(wig, wigC);
    cvt_tf32<<<cg, 256>>>(wf,  wfC);
    cvt_tf32<<<cg, 256>>>(wog, wogC);
    cvt_tf32<<<cg, 256>>>(wo,  woC);
    cvt_tf32<<<cg, 256>>>(fwi, fwiC);
    cvt_tf32<<<cg, 256>>>(fwg, fwgC);
    cvt_tf32<<<cg, 256>>>(fwo, fwoC);

    ln1024<<<R_ROWS, 256>>>(x, ln1w, ln1b, y);

    dim3 gM(M_DIM / 128, R_ROWS / 128);
    dim3 gE(E_DIM / 128, R_ROWS / 128);

    gemm_mma<<<gM, 256, GSMEM>>>(y, wiC,  nullptr, nullptr, b0, E_DIM, M_DIM, 0);
    gemm_mma<<<gM, 256, GSMEM>>>(y, wigC, wigb,    b0,      b1, E_DIM, M_DIM, 2); // yi fp32
    gemm_mma<<<gM, 256, GSMEM>>>(y, wfC,  wfb,     nullptr, rb, E_DIM, M_DIM, 1);
    gemm_mma<<<gM, 256, GSMEM>>>(y, wogC, wogb,    nullptr, og, E_DIM, M_DIM, 1);

    scan_pass1<<<NCHUNK * 8192 / 256, 256>>>(b1, rb, Ac, Sc);
    scan_pass2<<<8192 / 256, 256>>>(mem, Ac, Sc, Hc, out + (size_t)R_ROWS * E_DIM);
    scan_pass3<<<NCHUNK * 8192 / 256, 256>>>(b1, rb, og, Hc, g);

    gemm_mma<<<gE, 256, GSMEM>>>(g, woC, nullptr, x, x2, M_DIM, E_DIM, 3);

    ln1024<<<R_ROWS, 256>>>(x2, ln2w, ln2b, z);

    gemm_mma<<<gM, 256, GSMEM>>>(z,  fwiC, nullptr, nullptr, b0,  E_DIM, M_DIM, 0);
    gemm_mma<<<gM, 256, GSMEM>>>(z,  fwgC, fwgb,    b0,      b1,  E_DIM, M_DIM, 4); // zi tf32
    gemm_mma<<<gE, 256, GSMEM>>>(b1, fwoC, fwob,    x2,      out, M_DIM, E_DIM, 3);
}

// round 6
// speedup vs baseline: 1.0098x; 1.0098x over previous
#include <cuda_runtime.h>
#include <cstdint>
#include <math.h>

// Sizes fixed: B=4, T=2048, E=1024, M=2048; R = B*T = 8192.
#define R_ROWS 8192
#define E_DIM  1024
#define M_DIM  2048
#define NCHUNK 16
#define TCH    128

// ---------------- scratch ----------------
__device__ float g_y [R_ROWS * E_DIM];
__device__ float g_b0[R_ROWS * M_DIM];
__device__ float g_b1[R_ROWS * M_DIM];   // yi (fp32) / zi (tf32-truncated)
__device__ float g_r [R_ROWS * M_DIM];
__device__ float g_og[R_ROWS * M_DIM];
__device__ float g_g [R_ROWS * M_DIM];
__device__ float g_x2[R_ROWS * E_DIM];
__device__ float g_z [R_ROWS * E_DIM];
__device__ float g_Ac[NCHUNK * 8192];
__device__ float g_Sc[NCHUNK * 8192];
__device__ float g_Hc[NCHUNK * 8192];
#define WSLOT (E_DIM * M_DIM)
__device__ float g_wT[8 * WSLOT];        // tf32-truncated weights

__device__ __forceinline__ float sigm(float x) { return 1.f / (1.f + __expf(-x)); }

__device__ __forceinline__ uint32_t smem_u32(const void* p) {
    uint32_t a;
    asm("{ .reg .u64 t; cvta.to.shared.u64 t, %1; cvt.u32.u64 %0, t; }" : "=r"(a) : "l"(p));
    return a;
}

#define CP_ASYNC16(dst, src) asm volatile("cp.async.cg.shared.global [%0], [%1], 16;" :: "r"(dst), "l"(src))
#define CP_COMMIT()          asm volatile("cp.async.commit_group;" ::: "memory")
#define CP_WAIT2()           asm volatile("cp.async.wait_group 2;" ::: "memory")

__device__ __forceinline__ float f2tf32f(float v) {
    uint32_t r;
    asm("cvt.rna.tf32.f32 %0, %1;" : "=r"(r) : "f"(v));
    return __uint_as_float(r);
}

#define MMA_TF32(c, a, b)                                                      \
    asm volatile("mma.sync.aligned.m16n8k8.row.col.f32.tf32.tf32.f32 "         \
        "{%0,%1,%2,%3}, {%4,%5,%6,%7}, {%8,%9}, {%0,%1,%2,%3};"                \
        : "+f"((c)[0]), "+f"((c)[1]), "+f"((c)[2]), "+f"((c)[3])               \
        : "r"((a)[0]), "r"((a)[1]), "r"((a)[2]), "r"((a)[3]),                  \
          "r"((b)[0]), "r"((b)[1]))

// ---------------- weight convert: fp32 -> tf32(rna) bits, all 8 in one ----------------
struct CvtArgs { const float* s[8]; float* d[8]; };
__global__ __launch_bounds__(256) void cvt8_tf32(CvtArgs a) {
    int w = blockIdx.y;
    int i = blockIdx.x * 256 + threadIdx.x;
    float4 v = ((const float4*)a.s[w])[i];
    v.x = f2tf32f(v.x); v.y = f2tf32f(v.y); v.z = f2tf32f(v.z); v.w = f2tf32f(v.w);
    ((float4*)a.d[w])[i] = v;
}

// ---------------- LayerNorm (rows of 1024), tf32-truncated output ----------------
__global__ __launch_bounds__(256) void ln1024(const float* __restrict__ x,
                                              const float* __restrict__ w,
                                              const float* __restrict__ b,
                                              float* __restrict__ y) {
    int row = blockIdx.x;
    const float4* xr = (const float4*)(x + (size_t)row * 1024);
    float4 v = xr[threadIdx.x];
    float s = v.x + v.y + v.z + v.w;
    float q = v.x * v.x + v.y * v.y + v.z * v.z + v.w * v.w;
#pragma unroll
    for (int o = 16; o; o >>= 1) {
        s += __shfl_xor_sync(0xFFFFFFFF, s, o);
        q += __shfl_xor_sync(0xFFFFFFFF, q, o);
    }
    __shared__ float ss[8], sq[8];
    int wid = threadIdx.x >> 5, lane = threadIdx.x & 31;
    if (lane == 0) { ss[wid] = s; sq[wid] = q; }
    __syncthreads();
    s = 0.f; q = 0.f;
#pragma unroll
    for (int i = 0; i < 8; i++) { s += ss[i]; q += sq[i]; }
    float mu  = s * (1.f / 1024.f);
    float var = q * (1.f / 1024.f) - mu * mu;
    float inv = rsqrtf(var + 1e-5f);
    float4 wv = ((const float4*)w)[threadIdx.x];
    float4 bv = ((const float4*)b)[threadIdx.x];
    float4 o;
    o.x = f2tf32f((v.x - mu) * inv * wv.x + bv.x);
    o.y = f2tf32f((v.y - mu) * inv * wv.y + bv.y);
    o.z = f2tf32f((v.z - mu) * inv * wv.z + bv.z);
    o.w = f2tf32f((v.w - mu) * inv * wv.w + bv.w);
    ((float4*)(y + (size_t)row * 1024))[threadIdx.x] = o;
}

// ---------------- tf32 mma.sync GEMM, 4-stage cp.async pipeline ----------------
// C[m][n] = epi( sum_k A[m][k] * B[k][n] ),  A:[M,K] rm, B:[K,N] rm.
// mode 0: raw  1: sigmoid(acc+bias)  2: resid*sigmoid(acc+bias)
//      3: acc(+bias)+resid  4: tf32(resid*sigmoid(acc+bias))
// CTA tile 128x128, BK=16, 4 stages, 256 thr = 8 warps (4m x 2n), warp tile 32x64.
#define NSTG  4
#define ASTR  20                  // 16 + 4 pad (words)
#define AW    (128 * ASTR)        // 2560 words
#define BSTR  132                 // 128 + 4 pad
#define BW    (16 * BSTR)         // 2112 words
#define STW   (AW + BW)           // 4672 words / stage
#define GSMEM (NSTG * STW * 4)    // 74752 bytes

__global__ __launch_bounds__(256, 2) void gemm_mma(const float* __restrict__ A,
                                                   const float* __restrict__ B,
                                                   const float* __restrict__ bias,
                                                   const float* __restrict__ resid,
                                                   float* __restrict__ C,
                                                   int K, int N, int mode) {
    extern __shared__ char smem[];
    const uint32_t* swi = (const uint32_t*)smem;
    uint32_t sbase = smem_u32(smem);

    int tid = threadIdx.x;
    int wid = tid >> 5, lane = tid & 31;
    int wm = wid & 3, wn = wid >> 2;
    int m0 = wm * 32, n0 = wn * 64;
    int grp = lane >> 2, ktid = lane & 3;
    int brow = blockIdx.y * 128, bcol = blockIdx.x * 128;

    // A: 128 rows x 16 cols. thread -> row = tid>>1 (128), col = (tid&1)*8 (2x8)
    const float* gA = A + (size_t)(brow + (tid >> 1)) * K + (tid & 1) * 8;
    uint32_t dA = sbase + (uint32_t)((tid >> 1) * ASTR + (tid & 1) * 8) * 4;
    // B: 16 rows x 128 cols. thread -> row = tid>>4 (16), col = (tid&15)*8 (16x8)
    const float* gB = B + (size_t)(tid >> 4) * N + bcol + (tid & 15) * 8;
    uint32_t dB = sbase + (uint32_t)(AW + (tid >> 4) * BSTR + (tid & 15) * 8) * 4;

    float acc[2][8][4];
#pragma unroll
    for (int i = 0; i < 2; i++)
#pragma unroll
        for (int j = 0; j < 8; j++)
#pragma unroll
            for (int v = 0; v < 4; v++) acc[i][j][v] = 0.f;

    const int nk = K / 16;
    const int aoff0 = (m0 + grp) * ASTR + ktid;
    const int boff0 = ktid * BSTR + n0 + grp;

    // prologue: fill 3 stages
#pragma unroll
    for (int p = 0; p < NSTG - 1; p++) {
        const float* a = gA + p * 16;
        const float* b = gB + (size_t)p * 16 * N;
        uint32_t o = (uint32_t)p * (STW * 4);
        CP_ASYNC16(dA + o, a);      CP_ASYNC16(dA + o + 16, a + 4);
        CP_ASYNC16(dB + o, b);      CP_ASYNC16(dB + o + 16, b + 4);
        CP_COMMIT();
    }

    for (int kt = 0; kt < nk; kt++) {
        CP_WAIT2();
        __syncthreads();

        // issue next stage load before compute (3-deep prefetch)
        if (kt + NSTG - 1 < nk) {
            int s = (kt + NSTG - 1) & (NSTG - 1);
            const float* a = gA + (kt + NSTG - 1) * 16;
            const float* b = gB + (size_t)(kt + NSTG - 1) * 16 * N;
            uint32_t o = (uint32_t)s * (STW * 4);
            CP_ASYNC16(dA + o, a);      CP_ASYNC16(dA + o + 16, a + 4);
            CP_ASYNC16(dB + o, b);      CP_ASYNC16(dB + o + 16, b + 4);
        }
        CP_COMMIT();

        const uint32_t* cA = swi + (kt & (NSTG - 1)) * STW;
        const uint32_t* cB = cA + AW;

#pragma unroll
        for (int ks = 0; ks < 2; ks++) {
            uint32_t af[2][4], bf[8][2];
#pragma unroll
            for (int mi = 0; mi < 2; mi++) {
                const uint32_t* p = cA + aoff0 + mi * 16 * ASTR + ks * 8;
                af[mi][0] = p[0];
                af[mi][1] = p[8 * ASTR];
                af[mi][2] = p[4];
                af[mi][3] = p[8 * ASTR + 4];
            }
#pragma unroll
            for (int ni = 0; ni < 8; ni++) {
                const uint32_t* q = cB + boff0 + ks * 8 * BSTR + ni * 8;
                bf[ni][0] = q[0];
                bf[ni][1] = q[4 * BSTR];
            }
#pragma unroll
            for (int mi = 0; mi < 2; mi++)
#pragma unroll
                for (int ni = 0; ni < 8; ni++)
                    MMA_TF32(acc[mi][ni], af[mi], bf[ni]);
        }
    }

    // ---------------- epilogue ----------------
#pragma unroll
    for (int mi = 0; mi < 2; mi++) {
#pragma unroll
        for (int ni = 0; ni < 8; ni++) {
            int row = brow + m0 + mi * 16 + grp;
            int col = bcol + n0 + ni * 8 + ktid * 2;
            float b0v = 0.f, b1v = 0.f;
            if ((mode != 0) && bias) { b0v = bias[col]; b1v = bias[col + 1]; }
#pragma unroll
            for (int half = 0; half < 2; half++) {
                int r = row + half * 8;
                float v0 = acc[mi][ni][half * 2 + 0] + b0v;
                float v1 = acc[mi][ni][half * 2 + 1] + b1v;
                if (mode == 1 || mode == 2 || mode == 4) { v0 = sigm(v0); v1 = sigm(v1); }
                size_t off = (size_t)r * N + col;
                if (mode == 2 || mode == 4) {
                    float2 rr = *(const float2*)(resid + off);
                    v0 *= rr.x; v1 *= rr.y;
                    if (mode == 4) { v0 = f2tf32f(v0); v1 = f2tf32f(v1); }
                } else if (mode == 3) {
                    float2 rr = *(const float2*)(resid + off);
                    v0 += rr.x; v1 += rr.y;
                }
                float2 o; o.x = v0; o.y = v1;
                *(float2*)(C + off) = o;
            }
        }
    }
}

// ---------------- chunked scan: h_t = r_t*h_{t-1} + yi_t ----------------
__global__ __launch_bounds__(256) void scan_pass1(const float* __restrict__ yi,
                                                  const float* __restrict__ rb,
                                                  float* __restrict__ Ac,
                                                  float* __restrict__ Sc) {
    int idx = blockIdx.x * 256 + threadIdx.x;
    int ch  = idx & 8191;
    int c   = idx >> 13;
    int b   = ch >> 11;
    int base = (b * 2048 + c * TCH) * 2048 + (ch & 2047);
    float A = 1.f, S = 0.f;
#pragma unroll 4
    for (int t = 0; t < TCH; t++) {
        float rr = rb[base];
        S = fmaf(rr, S, yi[base]);
        A *= rr;
        base += 2048;
    }
    Ac[idx] = A;
    Sc[idx] = S;
}

__global__ __launch_bounds__(256) void scan_pass2(const float* __restrict__ mem,
                                                  const float* __restrict__ Ac,
                                                  const float* __restrict__ Sc,
                                                  float* __restrict__ Hc,
                                                  float* __restrict__ memout) {
    int ch = blockIdx.x * 256 + threadIdx.x;
    float h = mem[ch];
#pragma unroll
    for (int c = 0; c < NCHUNK; c++) {
        int i = c * 8192 + ch;
        Hc[i] = h;
        h = fmaf(Ac[i], h, Sc[i]);
    }
    memout[ch] = h;
}

__global__ __launch_bounds__(256) void scan_pass3(const float* __restrict__ yi,
                                                  const float* __restrict__ rb,
                                                  const float* __restrict__ og,
                                                  const float* __restrict__ Hc,
                                                  float* __restrict__ g) {
    int idx = blockIdx.x * 256 + threadIdx.x;
    int ch  = idx & 8191;
    int c   = idx >> 13;
    int b   = ch >> 11;
    int base = (b * 2048 + c * TCH) * 2048 + (ch & 2047);
    float h = Hc[idx];
#pragma unroll 4
    for (int t = 0; t < TCH; t++) {
        float rr = rb[base];
        h = fmaf(rr, h, yi[base]);
        float s = h / (1.f + fabsf(h));
        g[base] = f2tf32f(s * og[base]);   // tf32: g is GEMM-A-only
        base += 2048;
    }
}

// ---------------- host launch ----------------
extern "C" void kernel_launch(void* const* d_in, const int* in_sizes, int n_in,
                              void* d_out, int out_size) {
    const float* x    = (const float*)d_in[0];
    const float* mem  = (const float*)d_in[1];
    const float* ln1w = (const float*)d_in[2];
    const float* ln1b = (const float*)d_in[3];
    const float* wf   = (const float*)d_in[4];
    const float* wfb  = (const float*)d_in[5];
    const float* wi   = (const float*)d_in[6];
    const float* wig  = (const float*)d_in[7];
    const float* wigb = (const float*)d_in[8];
    const float* wog  = (const float*)d_in[9];
    const float* wogb = (const float*)d_in[10];
    const float* wo   = (const float*)d_in[11];
    const float* ln2w = (const float*)d_in[12];
    const float* ln2b = (const float*)d_in[13];
    const float* fwi  = (const float*)d_in[14];
    const float* fwg  = (const float*)d_in[15];
    const float* fwgb = (const float*)d_in[16];
    const float* fwo  = (const float*)d_in[17];
    const float* fwob = (const float*)d_in[18];
    float* out = (float*)d_out;

    float *y, *b0, *b1, *rb, *og, *g, *x2, *z, *Ac, *Sc, *Hc, *wT;
    cudaGetSymbolAddress((void**)&y,  g_y);
    cudaGetSymbolAddress((void**)&b0, g_b0);
    cudaGetSymbolAddress((void**)&b1, g_b1);
    cudaGetSymbolAddress((void**)&rb, g_r);
    cudaGetSymbolAddress((void**)&og, g_og);
    cudaGetSymbolAddress((void**)&g,  g_g);
    cudaGetSymbolAddress((void**)&x2, g_x2);
    cudaGetSymbolAddress((void**)&z,  g_z);
    cudaGetSymbolAddress((void**)&Ac, g_Ac);
    cudaGetSymbolAddress((void**)&Sc, g_Sc);
    cudaGetSymbolAddress((void**)&Hc, g_Hc);
    cudaGetSymbolAddress((void**)&wT, g_wT);

    cudaFuncSetAttribute(gemm_mma, cudaFuncAttributeMaxDynamicSharedMemorySize, GSMEM);

    float* wiC  = wT + 0 * WSLOT;
    float* wigC = wT + 1 * WSLOT;
    float* wfC  = wT + 2 * WSLOT;
    float* wogC = wT + 3 * WSLOT;
    float* woC  = wT + 4 * WSLOT;
    float* fwiC = wT + 5 * WSLOT;
    float* fwgC = wT + 6 * WSLOT;
    float* fwoC = wT + 7 * WSLOT;

    CvtArgs ca;
    ca.s[0] = wi;  ca.d[0] = wiC;
    ca.s[1] = wig; ca.d[1] = wigC;
    ca.s[2] = wf;  ca.d[2] = wfC;
    ca.s[3] = wog; ca.d[3] = wogC;
    ca.s[4] = wo;  ca.d[4] = woC;
    ca.s[5] = fwi; ca.d[5] = fwiC;
    ca.s[6] = fwg; ca.d[6] = fwgC;
    ca.s[7] = fwo; ca.d[7] = fwoC;
    dim3 cg(WSLOT / 4 / 256, 8);
    cvt8_tf32<<<cg, 256>>>(ca);

    ln1024<<<R_ROWS, 256>>>(x, ln1w, ln1b, y);

    dim3 gM(M_DIM / 128, R_ROWS / 128);
    dim3 gE(E_DIM / 128, R_ROWS / 128);

    gemm_mma<<<gM, 256, GSMEM>>>(y, wiC,  nullptr, nullptr, b0, E_DIM, M_DIM, 0);
    gemm_mma<<<gM, 256, GSMEM>>>(y, wigC, wigb,    b0,      b1, E_DIM, M_DIM, 2); // yi fp32
    gemm_mma<<<gM, 256, GSMEM>>>(y, wfC,  wfb,     nullptr, rb, E_DIM, M_DIM, 1);
    gemm_mma<<<gM, 256, GSMEM>>>(y, wogC, wogb,    nullptr, og, E_DIM, M_DIM, 1);

    scan_pass1<<<NCHUNK * 8192 / 256, 256>>>(b1, rb, Ac, Sc);
    scan_pass2<<<8192 / 256, 256>>>(mem, Ac, Sc, Hc, out + (size_t)R_ROWS * E_DIM);
    scan_pass3<<<NCHUNK * 8192 / 256, 256>>>(b1, rb, og, Hc, g);

    gemm_mma<<<gE, 256, GSMEM>>>(g, woC, nullptr, x, x2, M_DIM, E_DIM, 3);

    ln1024<<<R_ROWS, 256>>>(x2, ln2w, ln2b, z);

    gemm_mma<<<gM, 256, GSMEM>>>(z,  fwiC, nullptr, nullptr, b0,  E_DIM, M_DIM, 0);
    gemm_mma<<<gM, 256, GSMEM>>>(z,  fwgC, fwgb,    b0,      b1,  E_DIM, M_DIM, 4); // zi tf32
    gemm_mma<<<gE, 256, GSMEM>>>(b1, fwoC, fwob,    x2,      out, M_DIM, E_DIM, 3);
}

// round 7
// speedup vs baseline: 1.2006x; 1.1889x over previous
#include <cuda_runtime.h>
#include <cstdint>
#include <math.h>

// Sizes fixed: B=4, T=2048, E=1024, M=2048; R = B*T = 8192.
#define R_ROWS 8192
#define E_DIM  1024
#define M_DIM  2048
#define NCHUNK 16
#define TCH    128

// ---------------- scratch ----------------
__device__ float g_y [R_ROWS * E_DIM];
__device__ float g_b0[R_ROWS * M_DIM];
__device__ float g_b1[R_ROWS * M_DIM];   // yi (fp32) / zi (tf32-truncated)
__device__ float g_r [R_ROWS * M_DIM];
__device__ float g_og[R_ROWS * M_DIM];
__device__ float g_g [R_ROWS * M_DIM];
__device__ float g_x2[R_ROWS * E_DIM];
__device__ float g_z [R_ROWS * E_DIM];
__device__ float g_Ac[NCHUNK * 8192];
__device__ float g_Sc[NCHUNK * 8192];
__device__ float g_Hc[NCHUNK * 8192];
#define WSLOT (E_DIM * M_DIM)
__device__ float g_wT[8 * WSLOT];        // transposed + tf32-truncated weights [N][K]

__device__ __forceinline__ float sigm(float x) { return 1.f / (1.f + __expf(-x)); }

__device__ __forceinline__ uint32_t smem_u32(const void* p) {
    uint32_t a;
    asm("{ .reg .u64 t; cvta.to.shared.u64 t, %1; cvt.u32.u64 %0, t; }" : "=r"(a) : "l"(p));
    return a;
}

#define CP_ASYNC16(dst, src) asm volatile("cp.async.cg.shared.global [%0], [%1], 16;" :: "r"(dst), "l"(src))
#define CP_COMMIT()          asm volatile("cp.async.commit_group;" ::: "memory")
#define CP_WAIT2()           asm volatile("cp.async.wait_group 2;" ::: "memory")

__device__ __forceinline__ float f2tf32f(float v) {
    uint32_t r;
    asm("cvt.rna.tf32.f32 %0, %1;" : "=r"(r) : "f"(v));
    return __uint_as_float(r);
}

#define LDSM4(r0, r1, r2, r3, addr)                                            \
    asm volatile("ldmatrix.sync.aligned.m8n8.x4.shared.b16 {%0,%1,%2,%3}, [%4];" \
        : "=r"(r0), "=r"(r1), "=r"(r2), "=r"(r3) : "r"(addr))

#define MMA_TF32(c, a, b)                                                      \
    asm volatile("mma.sync.aligned.m16n8k8.row.col.f32.tf32.tf32.f32 "         \
        "{%0,%1,%2,%3}, {%4,%5,%6,%7}, {%8,%9}, {%0,%1,%2,%3};"                \
        : "+f"((c)[0]), "+f"((c)[1]), "+f"((c)[2]), "+f"((c)[3])               \
        : "r"((a)[0]), "r"((a)[1]), "r"((a)[2]), "r"((a)[3]),                  \
          "r"((b)[0]), "r"((b)[1]))

// ---------------- fused transpose + tf32 truncate: src[K][N] -> dst[N][K] ----------------
__global__ __launch_bounds__(256) void tcvt(const float* __restrict__ src,
                                            float* __restrict__ dst, int K, int N) {
    __shared__ float t[32][33];
    int bx = blockIdx.x * 32;  // n
    int by = blockIdx.y * 32;  // k
#pragma unroll
    for (int i = threadIdx.y; i < 32; i += 8)
        t[i][threadIdx.x] = src[(size_t)(by + i) * N + bx + threadIdx.x];
    __syncthreads();
#pragma unroll
    for (int i = threadIdx.y; i < 32; i += 8)
        dst[(size_t)(bx + i) * K + by + threadIdx.x] = f2tf32f(t[threadIdx.x][i]);
}

// ---------------- LayerNorm (rows of 1024), tf32-truncated output ----------------
__global__ __launch_bounds__(256) void ln1024(const float* __restrict__ x,
                                              const float* __restrict__ w,
                                              const float* __restrict__ b,
                                              float* __restrict__ y) {
    int row = blockIdx.x;
    const float4* xr = (const float4*)(x + (size_t)row * 1024);
    float4 v = xr[threadIdx.x];
    float s = v.x + v.y + v.z + v.w;
    float q = v.x * v.x + v.y * v.y + v.z * v.z + v.w * v.w;
#pragma unroll
    for (int o = 16; o; o >>= 1) {
        s += __shfl_xor_sync(0xFFFFFFFF, s, o);
        q += __shfl_xor_sync(0xFFFFFFFF, q, o);
    }
    __shared__ float ss[8], sq[8];
    int wid = threadIdx.x >> 5, lane = threadIdx.x & 31;
    if (lane == 0) { ss[wid] = s; sq[wid] = q; }
    __syncthreads();
    s = 0.f; q = 0.f;
#pragma unroll
    for (int i = 0; i < 8; i++) { s += ss[i]; q += sq[i]; }
    float mu  = s * (1.f / 1024.f);
    float var = q * (1.f / 1024.f) - mu * mu;
    float inv = rsqrtf(var + 1e-5f);
    float4 wv = ((const float4*)w)[threadIdx.x];
    float4 bv = ((const float4*)b)[threadIdx.x];
    float4 o;
    o.x = f2tf32f((v.x - mu) * inv * wv.x + bv.x);
    o.y = f2tf32f((v.y - mu) * inv * wv.y + bv.y);
    o.z = f2tf32f((v.z - mu) * inv * wv.z + bv.z);
    o.w = f2tf32f((v.w - mu) * inv * wv.w + bv.w);
    ((float4*)(y + (size_t)row * 1024))[threadIdx.x] = o;
}

// ---------------- tf32 mma GEMM with ldmatrix fragments ----------------
// C[m][n] = epi( sum_k A[m][k] * Bt[n][k] ),  A:[M,K] rm, Bt:[N,K] rm (both K-major).
// mode 0: raw  1: sigmoid(acc+bias)  2: resid*sigmoid(acc+bias)
//      3: acc(+bias)+resid  4: tf32(resid*sigmoid(acc+bias))
// CTA 128x128, BK=16, 4 stages. 256 thr = 8 warps (4m x 2n), warp tile 32x64.
#define NSTG  4
#define AST   20                    // 16 + 4 pad (words) -> conflict-free ldmatrix
#define AWRD  (128 * AST)           // words per tile (A or B)
#define STGW  (2 * AWRD)            // 5120 words / stage
#define GSMEM (NSTG * STGW * 4)     // 81920 bytes

__global__ __launch_bounds__(256, 2) void gemm_mma(const float* __restrict__ A,
                                                   const float* __restrict__ Bt,
                                                   const float* __restrict__ bias,
                                                   const float* __restrict__ resid,
                                                   float* __restrict__ C,
                                                   int K, int N, int mode) {
    extern __shared__ char smem[];
    uint32_t sbase = smem_u32(smem);

    int tid = threadIdx.x;
    int wid = tid >> 5, lane = tid & 31;
    int wm = wid & 3, wn = wid >> 2;
    int m0 = wm * 32, n0 = wn * 64;
    int grp = lane >> 2, ktid = lane & 3;
    int brow = blockIdx.y * 128, bcol = blockIdx.x * 128;

    // loads: both tiles 128 rows x 16 k-words. thread -> row = tid>>1, cw = (tid&1)*8
    int lrow = tid >> 1, lcw = (tid & 1) * 8;
    const float* gA = A  + (size_t)(brow + lrow) * K + lcw;
    const float* gB = Bt + (size_t)(bcol + lrow) * K + lcw;
    uint32_t dA = sbase + (uint32_t)(lrow * AST + lcw) * 4;
    uint32_t dB = sbase + (uint32_t)(AWRD + lrow * AST + lcw) * 4;

    // ldmatrix per-lane row addresses: quadrants M0..M3 of a 16row x 8col(b32) block
    int l7 = lane & 7, lq = (lane >> 3) & 1, lh = lane >> 4;
    uint32_t aB = sbase + (uint32_t)(((m0 + lq * 8 + l7) * AST + lh * 4) * 4);
    uint32_t bB = sbase + (uint32_t)((AWRD + (n0 + lq * 8 + l7) * AST + lh * 4) * 4);

    float acc[2][8][4];
#pragma unroll
    for (int i = 0; i < 2; i++)
#pragma unroll
        for (int j = 0; j < 8; j++)
#pragma unroll
            for (int v = 0; v < 4; v++) acc[i][j][v] = 0.f;

    const int nk = K / 16;

    // prologue: fill 3 stages
#pragma unroll
    for (int p = 0; p < NSTG - 1; p++) {
        uint32_t o = (uint32_t)p * (STGW * 4);
        const float* a = gA + p * 16;
        const float* b = gB + p * 16;
        CP_ASYNC16(dA + o, a);      CP_ASYNC16(dA + o + 16, a + 4);
        CP_ASYNC16(dB + o, b);      CP_ASYNC16(dB + o + 16, b + 4);
        CP_COMMIT();
    }

    for (int kt = 0; kt < nk; kt++) {
        CP_WAIT2();
        __syncthreads();

        if (kt + NSTG - 1 < nk) {
            uint32_t o = (uint32_t)((kt + NSTG - 1) & (NSTG - 1)) * (STGW * 4);
            const float* a = gA + (kt + NSTG - 1) * 16;
            const float* b = gB + (kt + NSTG - 1) * 16;
            CP_ASYNC16(dA + o, a);      CP_ASYNC16(dA + o + 16, a + 4);
            CP_ASYNC16(dB + o, b);      CP_ASYNC16(dB + o + 16, b + 4);
        }
        CP_COMMIT();

        uint32_t so = (uint32_t)(kt & (NSTG - 1)) * (STGW * 4);

#pragma unroll
        for (int ks = 0; ks < 2; ks++) {
            uint32_t af[2][4], bf[8][2];
#pragma unroll
            for (int mi = 0; mi < 2; mi++)
                LDSM4(af[mi][0], af[mi][1], af[mi][2], af[mi][3],
                      aB + so + (uint32_t)(mi * 16 * AST * 4) + (uint32_t)(ks * 32));
#pragma unroll
            for (int p = 0; p < 4; p++)
                LDSM4(bf[2 * p][0], bf[2 * p + 1][0], bf[2 * p][1], bf[2 * p + 1][1],
                      bB + so + (uint32_t)(p * 16 * AST * 4) + (uint32_t)(ks * 32));
#pragma unroll
            for (int mi = 0; mi < 2; mi++)
#pragma unroll
                for (int ni = 0; ni < 8; ni++)
                    MMA_TF32(acc[mi][ni], af[mi], bf[ni]);
        }
    }

    // ---------------- epilogue ----------------
#pragma unroll
    for (int mi = 0; mi < 2; mi++) {
#pragma unroll
        for (int ni = 0; ni < 8; ni++) {
            int row = brow + m0 + mi * 16 + grp;
            int col = bcol + n0 + ni * 8 + ktid * 2;
            float b0v = 0.f, b1v = 0.f;
            if ((mode != 0) && bias) { b0v = bias[col]; b1v = bias[col + 1]; }
#pragma unroll
            for (int half = 0; half < 2; half++) {
                int r = row + half * 8;
                float v0 = acc[mi][ni][half * 2 + 0] + b0v;
                float v1 = acc[mi][ni][half * 2 + 1] + b1v;
                if (mode == 1 || mode == 2 || mode == 4) { v0 = sigm(v0); v1 = sigm(v1); }
                size_t off = (size_t)r * N + col;
                if (mode == 2 || mode == 4) {
                    float2 rr = *(const float2*)(resid + off);
                    v0 *= rr.x; v1 *= rr.y;
                    if (mode == 4) { v0 = f2tf32f(v0); v1 = f2tf32f(v1); }
                } else if (mode == 3) {
                    float2 rr = *(const float2*)(resid + off);
                    v0 += rr.x; v1 += rr.y;
                }
                float2 o; o.x = v0; o.y = v1;
                *(float2*)(C + off) = o;
            }
        }
    }
}

// ---------------- chunked scan: h_t = r_t*h_{t-1} + yi_t ----------------
__global__ __launch_bounds__(256) void scan_pass1(const float* __restrict__ yi,
                                                  const float* __restrict__ rb,
                                                  float* __restrict__ Ac,
                                                  float* __restrict__ Sc) {
    int idx = blockIdx.x * 256 + threadIdx.x;
    int ch  = idx & 8191;
    int c   = idx >> 13;
    int b   = ch >> 11;
    int base = (b * 2048 + c * TCH) * 2048 + (ch & 2047);
    float A = 1.f, S = 0.f;
#pragma unroll 4
    for (int t = 0; t < TCH; t++) {
        float rr = rb[base];
        S = fmaf(rr, S, yi[base]);
        A *= rr;
        base += 2048;
    }
    Ac[idx] = A;
    Sc[idx] = S;
}

__global__ __launch_bounds__(256) void scan_pass2(const float* __restrict__ mem,
                                                  const float* __restrict__ Ac,
                                                  const float* __restrict__ Sc,
                                                  float* __restrict__ Hc,
                                                  float* __restrict__ memout) {
    int ch = blockIdx.x * 256 + threadIdx.x;
    float h = mem[ch];
#pragma unroll
    for (int c = 0; c < NCHUNK; c++) {
        int i = c * 8192 + ch;
        Hc[i] = h;
        h = fmaf(Ac[i], h, Sc[i]);
    }
    memout[ch] = h;
}

__global__ __launch_bounds__(256) void scan_pass3(const float* __restrict__ yi,
                                                  const float* __restrict__ rb,
                                                  const float* __restrict__ og,
                                                  const float* __restrict__ Hc,
                                                  float* __restrict__ g) {
    int idx = blockIdx.x * 256 + threadIdx.x;
    int ch  = idx & 8191;
    int c   = idx >> 13;
    int b   = ch >> 11;
    int base = (b * 2048 + c * TCH) * 2048 + (ch & 2047);
    float h = Hc[idx];
#pragma unroll 4
    for (int t = 0; t < TCH; t++) {
        float rr = rb[base];
        h = fmaf(rr, h, yi[base]);
        float s = h / (1.f + fabsf(h));
        g[base] = f2tf32f(s * og[base]);   // tf32: g is GEMM-A-only
        base += 2048;
    }
}

// ---------------- host launch ----------------
extern "C" void kernel_launch(void* const* d_in, const int* in_sizes, int n_in,
                              void* d_out, int out_size) {
    const float* x    = (const float*)d_in[0];
    const float* mem  = (const float*)d_in[1];
    const float* ln1w = (const float*)d_in[2];
    const float* ln1b = (const float*)d_in[3];
    const float* wf   = (const float*)d_in[4];
    const float* wfb  = (const float*)d_in[5];
    const float* wi   = (const float*)d_in[6];
    const float* wig  = (const float*)d_in[7];
    const float* wigb = (const float*)d_in[8];
    const float* wog  = (const float*)d_in[9];
    const float* wogb = (const float*)d_in[10];
    const float* wo   = (const float*)d_in[11];
    const float* ln2w = (const float*)d_in[12];
    const float* ln2b = (const float*)d_in[13];
    const float* fwi  = (const float*)d_in[14];
    const float* fwg  = (const float*)d_in[15];
    const float* fwgb = (const float*)d_in[16];
    const float* fwo  = (const float*)d_in[17];
    const float* fwob = (const float*)d_in[18];
    float* out = (float*)d_out;

    float *y, *b0, *b1, *rb, *og, *g, *x2, *z, *Ac, *Sc, *Hc, *wT;
    cudaGetSymbolAddress((void**)&y,  g_y);
    cudaGetSymbolAddress((void**)&b0, g_b0);
    cudaGetSymbolAddress((void**)&b1, g_b1);
    cudaGetSymbolAddress((void**)&rb, g_r);
    cudaGetSymbolAddress((void**)&og, g_og);
    cudaGetSymbolAddress((void**)&g,  g_g);
    cudaGetSymbolAddress((void**)&x2, g_x2);
    cudaGetSymbolAddress((void**)&z,  g_z);
    cudaGetSymbolAddress((void**)&Ac, g_Ac);
    cudaGetSymbolAddress((void**)&Sc, g_Sc);
    cudaGetSymbolAddress((void**)&Hc, g_Hc);
    cudaGetSymbolAddress((void**)&wT, g_wT);

    cudaFuncSetAttribute(gemm_mma, cudaFuncAttributeMaxDynamicSharedMemorySize, GSMEM);

    float* wiT  = wT + 0 * WSLOT;
    float* wigT = wT + 1 * WSLOT;
    float* wfT  = wT + 2 * WSLOT;
    float* wogT = wT + 3 * WSLOT;
    float* woT  = wT + 4 * WSLOT;
    float* fwiT = wT + 5 * WSLOT;
    float* fwgT = wT + 6 * WSLOT;
    float* fwoT = wT + 7 * WSLOT;

    dim3 tb(32, 8);
    dim3 tgEM(M_DIM / 32, E_DIM / 32);   // src [E][M]
    dim3 tgME(E_DIM / 32, M_DIM / 32);   // src [M][E]
    tcvt<<<tgEM, tb>>>(wi,  wiT,  E_DIM, M_DIM);
    tcvt<<<tgEM, tb>>>(wig, wigT, E_DIM, M_DIM);
    tcvt<<<tgEM, tb>>>(wf,  wfT,  E_DIM, M_DIM);
    tcvt<<<tgEM, tb>>>(wog, wogT, E_DIM, M_DIM);
    tcvt<<<tgME, tb>>>(wo,  woT,  M_DIM, E_DIM);
    tcvt<<<tgEM, tb>>>(fwi, fwiT, E_DIM, M_DIM);
    tcvt<<<tgEM, tb>>>(fwg, fwgT, E_DIM, M_DIM);
    tcvt<<<tgME, tb>>>(fwo, fwoT, M_DIM, E_DIM);

    ln1024<<<R_ROWS, 256>>>(x, ln1w, ln1b, y);

    dim3 gM(M_DIM / 128, R_ROWS / 128);
    dim3 gE(E_DIM / 128, R_ROWS / 128);

    gemm_mma<<<gM, 256, GSMEM>>>(y, wiT,  nullptr, nullptr, b0, E_DIM, M_DIM, 0);
    gemm_mma<<<gM, 256, GSMEM>>>(y, wigT, wigb,    b0,      b1, E_DIM, M_DIM, 2); // yi fp32
    gemm_mma<<<gM, 256, GSMEM>>>(y, wfT,  wfb,     nullptr, rb, E_DIM, M_DIM, 1);
    gemm_mma<<<gM, 256, GSMEM>>>(y, wogT, wogb,    nullptr, og, E_DIM, M_DIM, 1);

    scan_pass1<<<NCHUNK * 8192 / 256, 256>>>(b1, rb, Ac, Sc);
    scan_pass2<<<8192 / 256, 256>>>(mem, Ac, Sc, Hc, out + (size_t)R_ROWS * E_DIM);
    scan_pass3<<<NCHUNK * 8192 / 256, 256>>>(b1, rb, og, Hc, g);

    gemm_mma<<<gE, 256, GSMEM>>>(g, woT, nullptr, x, x2, M_DIM, E_DIM, 3);

    ln1024<<<R_ROWS, 256>>>(x2, ln2w, ln2b, z);

    gemm_mma<<<gM, 256, GSMEM>>>(z,  fwiT, nullptr, nullptr, b0,  E_DIM, M_DIM, 0);
    gemm_mma<<<gM, 256, GSMEM>>>(z,  fwgT, fwgb,    b0,      b1,  E_DIM, M_DIM, 4); // zi tf32
    gemm_mma<<<gE, 256, GSMEM>>>(b1, fwoT, fwob,    x2,      out, M_DIM, E_DIM, 3);
}